// round 5
// baseline (speedup 1.0000x reference)
#include <cuda_runtime.h>
#include <cuda_bf16.h>
#include <cstddef>

// ---------------------------------------------------------------------------
// CausalSelfAttention  B=4 T=2048 C=1024 H=16 HD=64  (fp32 end-to-end)
//   k1: qkv = x @ w_qkv                  (8192x3072, K=1024)
//   k2: flash attention per (b,h,qtile)  (causal, online softmax)
//   k3: out = y @ w_proj + b_proj        (8192x1024, K=1024)
// All heavy math uses packed fma.rn.f32x2 (FFMA2) -> 2x fp32 throughput.
// ---------------------------------------------------------------------------

#define BB   4
#define TT   2048
#define CC   1024
#define HH   16
#define HDIM 64
#define C3   3072

typedef unsigned long long u64;

__device__ __forceinline__ u64 pack2(float lo, float hi) {
    u64 r; asm("mov.b64 %0,{%1,%2};" : "=l"(r) : "f"(lo), "f"(hi)); return r;
}
__device__ __forceinline__ float2 unpack2(u64 v) {
    float2 f; asm("mov.b64 {%0,%1},%2;" : "=f"(f.x), "=f"(f.y) : "l"(v)); return f;
}
__device__ __forceinline__ u64 ffma2(u64 a, u64 b, u64 c) {
    u64 d; asm("fma.rn.f32x2 %0,%1,%2,%3;" : "=l"(d) : "l"(a), "l"(b), "l"(c)); return d;
}
__device__ __forceinline__ u64 fmul2(u64 a, u64 b) {
    u64 d; asm("mul.rn.f32x2 %0,%1,%2;" : "=l"(d) : "l"(a), "l"(b)); return d;
}

// Scratch (allocation-guard safe: __device__ globals)
__device__ float g_qkv[(size_t)BB * TT * C3];   // ~100.7 MB
__device__ float g_y  [(size_t)BB * TT * CC];   // ~33.6 MB

// ---------------------------------------------------------------------------
// SGEMM: C[M,N] = A[M,K] @ B[K,N] (+bias). 128x128 block, BK=8, 8x8/thread.
// ---------------------------------------------------------------------------
template<int M, int N, int K, bool BIAS>
__global__ __launch_bounds__(256, 2)
void sgemm128(const float* __restrict__ A, const float* __restrict__ B,
              const float* __restrict__ bias, float* __restrict__ Cc)
{
    __shared__ float As[8][128];   // A transposed: As[k][m]
    __shared__ float Bs[8][128];   // Bs[k][n]

    const int tid = threadIdx.x;
    const int bm0 = blockIdx.y * 128;
    const int bn0 = blockIdx.x * 128;

    const int rowA = tid >> 1;          // 0..127
    const int colA = (tid & 1) << 2;    // 0 or 4
    const int rowB = tid >> 5;          // 0..7
    const int colB = (tid & 31) << 2;   // 0..124

    const float* Ag = A + (size_t)(bm0 + rowA) * K + colA;
    const float* Bg = B + (size_t)rowB * N + bn0 + colB;

    const int tr = tid >> 4;            // 0..15
    const int tc = tid & 15;            // 0..15
    const int m0 = tr << 3;
    const int n0 = tc << 3;

    // Hoist bias load before the main loop (independent of GEMM dataflow).
    float bvals[8];
    if (BIAS) {
        #pragma unroll
        for (int j = 0; j < 8; j++) bvals[j] = bias[bn0 + n0 + j];
    } else {
        #pragma unroll
        for (int j = 0; j < 8; j++) bvals[j] = 0.0f;
    }

    u64 acc[8][4];
    #pragma unroll
    for (int m = 0; m < 8; m++)
        #pragma unroll
        for (int j = 0; j < 4; j++) acc[m][j] = 0ull;

    float4 pa = *(const float4*)Ag;
    float4 pb = *(const float4*)Bg;

    const int NK = K / 8;
    for (int kb = 0; kb < NK; kb++) {
        As[colA + 0][rowA] = pa.x;
        As[colA + 1][rowA] = pa.y;
        As[colA + 2][rowA] = pa.z;
        As[colA + 3][rowA] = pa.w;
        *(float4*)&Bs[rowB][colB] = pb;
        __syncthreads();

        if (kb + 1 < NK) {
            pa = *(const float4*)(Ag + (kb + 1) * 8);
            pb = *(const float4*)(Bg + (size_t)(kb + 1) * 8 * N);
        }

        #pragma unroll
        for (int k = 0; k < 8; k++) {
            float4 a0 = *(const float4*)&As[k][m0];
            float4 a1 = *(const float4*)&As[k][m0 + 4];
            float4 b0 = *(const float4*)&Bs[k][n0];
            float4 b1 = *(const float4*)&Bs[k][n0 + 4];
            u64 bb[4] = { pack2(b0.x, b0.y), pack2(b0.z, b0.w),
                          pack2(b1.x, b1.y), pack2(b1.z, b1.w) };
            float am[8] = { a0.x, a0.y, a0.z, a0.w, a1.x, a1.y, a1.z, a1.w };
            #pragma unroll
            for (int m = 0; m < 8; m++) {
                u64 am2 = pack2(am[m], am[m]);
                #pragma unroll
                for (int j = 0; j < 4; j++)
                    acc[m][j] = ffma2(am2, bb[j], acc[m][j]);
            }
        }
        __syncthreads();
    }

    #pragma unroll
    for (int m = 0; m < 8; m++) {
        float2 f0 = unpack2(acc[m][0]);
        float2 f1 = unpack2(acc[m][1]);
        float2 f2 = unpack2(acc[m][2]);
        float2 f3 = unpack2(acc[m][3]);
        float4 o0 = { f0.x + bvals[0], f0.y + bvals[1], f1.x + bvals[2], f1.y + bvals[3] };
        float4 o1 = { f2.x + bvals[4], f2.y + bvals[5], f3.x + bvals[6], f3.y + bvals[7] };
        float* cp = Cc + (size_t)(bm0 + m0 + m) * N + bn0 + n0;
        *(float4*)cp       = o0;
        *(float4*)(cp + 4) = o1;
    }
}

// ---------------------------------------------------------------------------
// Flash attention. One block = (b, h, 64-row q tile). 128 threads.
// Thread tile: 4 q-rows x 8 keys (S), 4 q-rows x 8 hd (O).
// Row <-> 8-lane shfl group; P broadcast via shfl (no smem for P).
// ---------------------------------------------------------------------------
__global__ __launch_bounds__(128, 3)
void attn64(const float* __restrict__ qkv, float* __restrict__ y)
{
    __shared__ float Qt[64][64];   // Q transposed, pre-scaled: Qt[d][row]
    __shared__ float Kt[64][64];   // K transposed: Kt[d][key]
    __shared__ float Vs[64][64];   // V: Vs[key][d]

    const int tid  = threadIdx.x;
    const int qt   = blockIdx.x & 31;
    const int h    = (blockIdx.x >> 5) & 15;
    const int b    = blockIdx.x >> 9;
    const int ty   = tid >> 3;          // 0..15  -> rows 4*ty..
    const int tx   = tid & 7;           // 0..7   -> keys/hd 8*tx..
    const int lane = tid & 31;
    const unsigned src_base = (unsigned)(lane & 24);   // start of 8-lane row group

    // Load + transpose + pre-scale Q tile (scale = HD^-0.5 = 0.125)
    {
        const int r  = tid >> 1;
        const int d0 = (tid & 1) << 5;
        const float* qrow = qkv + ((size_t)(b * TT + qt * 64 + r)) * C3 + h * HDIM + d0;
        #pragma unroll
        for (int i = 0; i < 8; i++) {
            float4 v = *(const float4*)(qrow + 4 * i);
            Qt[d0 + 4 * i + 0][r] = v.x * 0.125f;
            Qt[d0 + 4 * i + 1][r] = v.y * 0.125f;
            Qt[d0 + 4 * i + 2][r] = v.z * 0.125f;
            Qt[d0 + 4 * i + 3][r] = v.w * 0.125f;
        }
    }

    float m_[4], l_[4];
    u64 O2[4][4];
    #pragma unroll
    for (int i = 0; i < 4; i++) {
        m_[i] = -1e30f; l_[i] = 0.0f;
        #pragma unroll
        for (int j = 0; j < 4; j++) O2[i][j] = 0ull;
    }

    for (int kt = 0; kt <= qt; kt++) {
        __syncthreads();   // previous tile fully consumed
        {
            const int r  = tid >> 1;
            const int d0 = (tid & 1) << 5;
            const float* base = qkv + ((size_t)(b * TT + kt * 64 + r)) * C3 + h * HDIM + d0;
            #pragma unroll
            for (int i = 0; i < 8; i++) {
                float4 kv = *(const float4*)(base + CC + 4 * i);      // K
                Kt[d0 + 4 * i + 0][r] = kv.x;
                Kt[d0 + 4 * i + 1][r] = kv.y;
                Kt[d0 + 4 * i + 2][r] = kv.z;
                Kt[d0 + 4 * i + 3][r] = kv.w;
            }
            #pragma unroll
            for (int i = 0; i < 8; i++) {
                *(float4*)&Vs[r][d0 + 4 * i] = *(const float4*)(base + 2 * CC + 4 * i);  // V
            }
        }
        __syncthreads();

        // ---- S = Qs @ K^T  (4 rows x 8 keys per thread, FFMA2 pairs) ----
        u64 s2[4][4];
        #pragma unroll
        for (int i = 0; i < 4; i++)
            #pragma unroll
            for (int j = 0; j < 4; j++) s2[i][j] = 0ull;

        #pragma unroll 4
        for (int d = 0; d < 64; d++) {
            float4 q4 = *(const float4*)&Qt[d][ty << 2];
            float4 ka = *(const float4*)&Kt[d][tx << 3];
            float4 kb = *(const float4*)&Kt[d][(tx << 3) + 4];
            u64 kk[4] = { pack2(ka.x, ka.y), pack2(ka.z, ka.w),
                          pack2(kb.x, kb.y), pack2(kb.z, kb.w) };
            float qm[4] = { q4.x, q4.y, q4.z, q4.w };
            #pragma unroll
            for (int i = 0; i < 4; i++) {
                u64 q2 = pack2(qm[i], qm[i]);
                #pragma unroll
                for (int j = 0; j < 4; j++)
                    s2[i][j] = ffma2(q2, kk[j], s2[i][j]);
            }
        }

        float p[4][8];
        #pragma unroll
        for (int i = 0; i < 4; i++) {
            #pragma unroll
            for (int j = 0; j < 4; j++) {
                float2 f = unpack2(s2[i][j]);
                p[i][2 * j]     = f.x;
                p[i][2 * j + 1] = f.y;
            }
        }

        if (kt == qt) {   // causal mask on diagonal tile
            #pragma unroll
            for (int i = 0; i < 4; i++) {
                const int r = (ty << 2) + i;
                #pragma unroll
                for (int j = 0; j < 8; j++)
                    if ((tx << 3) + j > r) p[i][j] = -1e30f;
            }
        }

        // ---- online softmax (row stats replicated across 8-lane group) ----
        #pragma unroll
        for (int i = 0; i < 4; i++) {
            float mx = p[i][0];
            #pragma unroll
            for (int j = 1; j < 8; j++) mx = fmaxf(mx, p[i][j]);
            mx = fmaxf(mx, __shfl_xor_sync(0xffffffffu, mx, 1));
            mx = fmaxf(mx, __shfl_xor_sync(0xffffffffu, mx, 2));
            mx = fmaxf(mx, __shfl_xor_sync(0xffffffffu, mx, 4));
            float mn = fmaxf(m_[i], mx);
            float al = __expf(m_[i] - mn);
            m_[i] = mn;
            float rs = 0.0f;
            #pragma unroll
            for (int j = 0; j < 8; j++) {
                float e = __expf(p[i][j] - mn);
                p[i][j] = e;
                rs += e;
            }
            rs += __shfl_xor_sync(0xffffffffu, rs, 1);
            rs += __shfl_xor_sync(0xffffffffu, rs, 2);
            rs += __shfl_xor_sync(0xffffffffu, rs, 4);
            l_[i] = l_[i] * al + rs;
            u64 a2 = pack2(al, al);
            #pragma unroll
            for (int j = 0; j < 4; j++) O2[i][j] = fmul2(O2[i][j], a2);
        }

        // ---- O += P @ V : P broadcast via shfl (owner is in-warp) ----
        #pragma unroll 2
        for (int kq = 0; kq < 8; kq++) {
            const unsigned src = src_base + (unsigned)kq;
            #pragma unroll
            for (int kj = 0; kj < 8; kj++) {
                const int key = (kq << 3) + kj;
                float4 va = *(const float4*)&Vs[key][tx << 3];
                float4 vb = *(const float4*)&Vs[key][(tx << 3) + 4];
                u64 vv[4] = { pack2(va.x, va.y), pack2(va.z, va.w),
                              pack2(vb.x, vb.y), pack2(vb.z, vb.w) };
                float pp0 = __shfl_sync(0xffffffffu, p[0][kj], src);
                float pp1 = __shfl_sync(0xffffffffu, p[1][kj], src);
                float pp2 = __shfl_sync(0xffffffffu, p[2][kj], src);
                float pp3 = __shfl_sync(0xffffffffu, p[3][kj], src);
                float pp[4] = { pp0, pp1, pp2, pp3 };
                #pragma unroll
                for (int i = 0; i < 4; i++) {
                    u64 p2 = pack2(pp[i], pp[i]);
                    #pragma unroll
                    for (int j = 0; j < 4; j++)
                        O2[i][j] = ffma2(p2, vv[j], O2[i][j]);
                }
            }
        }
    }

    // ---- normalize + write y[b, t, h*64 + hd] ----
    #pragma unroll
    for (int i = 0; i < 4; i++) {
        float inv = 1.0f / l_[i];
        float2 f0 = unpack2(O2[i][0]);
        float2 f1 = unpack2(O2[i][1]);
        float2 f2 = unpack2(O2[i][2]);
        float2 f3 = unpack2(O2[i][3]);
        float4 o0 = { f0.x * inv, f0.y * inv, f1.x * inv, f1.y * inv };
        float4 o1 = { f2.x * inv, f2.y * inv, f3.x * inv, f3.y * inv };
        const int row = qt * 64 + (ty << 2) + i;
        float* yp = y + ((size_t)(b * TT + row)) * CC + h * HDIM + (tx << 3);
        *(float4*)yp       = o0;
        *(float4*)(yp + 4) = o1;
    }
}

// ---------------------------------------------------------------------------
extern "C" void kernel_launch(void* const* d_in, const int* in_sizes, int n_in,
                              void* d_out, int out_size)
{
    (void)in_sizes; (void)n_in; (void)out_size;
    const float* x      = (const float*)d_in[0];
    const float* w_qkv  = (const float*)d_in[1];
    const float* w_proj = (const float*)d_in[2];
    const float* b_proj = (const float*)d_in[3];
    float* out = (float*)d_out;

    void *pq = nullptr, *py = nullptr;
    cudaGetSymbolAddress(&pq, g_qkv);
    cudaGetSymbolAddress(&py, g_y);
    float* qkv = (float*)pq;
    float* yb  = (float*)py;

    // qkv = x @ w_qkv     [8192,1024] x [1024,3072]
    {
        dim3 grid(C3 / 128, (BB * TT) / 128);
        sgemm128<BB * TT, C3, CC, false><<<grid, 256>>>(x, w_qkv, nullptr, qkv);
    }
    // flash attention -> y
    {
        dim3 grid(BB * HH * (TT / 64));
        attn64<<<grid, 128>>>(qkv, yb);
    }
    // out = y @ w_proj + b_proj   [8192,1024] x [1024,1024]
    {
        dim3 grid(CC / 128, (BB * TT) / 128);
        sgemm128<BB * TT, CC, CC, true><<<grid, 256>>>(yb, w_proj, b_proj, out);
    }
}

// round 7
// speedup vs baseline: 1.3712x; 1.3712x over previous
#include <cuda_runtime.h>
#include <cuda_bf16.h>
#include <cstdint>
#include <cstddef>

// ---------------------------------------------------------------------------
// CausalSelfAttention  B=4 T=2048 C=1024 H=16 HD=64
//   conv:  x -> bf16 hi/lo ; W^T -> bf16 hi/lo (transposed)
//   k1:    qkv = x @ w_qkv        mma.sync bf16x3 (fp32-accurate)
//   k2:    flash attention (fp32, FFMA2) -> y as bf16 hi/lo
//   k3:    out = y @ w_proj + b   mma.sync bf16x3
// NOTE: harness PTX target is compute_103 (no 'a') -> tcgen05 unavailable.
//       mma.sync/ldmatrix are baseline PTX and run on the tensor pipe (HMMA).
// ---------------------------------------------------------------------------

#define BB   4
#define TT   2048
#define CC   1024
#define HH   16
#define HDIM 64
#define C3   3072
#define MTOT (BB*TT)            // 8192

typedef unsigned long long u64;
typedef unsigned int u32;

// ======================= PTX helpers =======================================
__device__ __forceinline__ u32 smem_u32(const void* p) {
    u32 a; asm("{ .reg .u64 t; cvta.to.shared.u64 t, %1; cvt.u32.u64 %0, t; }"
               : "=r"(a) : "l"(p));
    return a;
}
__device__ __forceinline__ void ldsm_x4(u32& r0, u32& r1, u32& r2, u32& r3, u32 addr) {
    asm volatile("ldmatrix.sync.aligned.m8n8.x4.shared.b16 {%0,%1,%2,%3},[%4];"
                 : "=r"(r0), "=r"(r1), "=r"(r2), "=r"(r3) : "r"(addr));
}
__device__ __forceinline__ void mma16816(float* d, const u32* a, const u32* b) {
    asm volatile("mma.sync.aligned.m16n8k16.row.col.f32.bf16.bf16.f32 "
                 "{%0,%1,%2,%3},{%4,%5,%6,%7},{%8,%9},{%0,%1,%2,%3};"
                 : "+f"(d[0]), "+f"(d[1]), "+f"(d[2]), "+f"(d[3])
                 : "r"(a[0]), "r"(a[1]), "r"(a[2]), "r"(a[3]),
                   "r"(b[0]), "r"(b[1]));
}

// fp32x2 helpers for attention
__device__ __forceinline__ u64 pack2(float lo, float hi) {
    u64 r; asm("mov.b64 %0,{%1,%2};" : "=l"(r) : "f"(lo), "f"(hi)); return r;
}
__device__ __forceinline__ float2 unpack2(u64 v) {
    float2 f; asm("mov.b64 {%0,%1},%2;" : "=f"(f.x), "=f"(f.y) : "l"(v)); return f;
}
__device__ __forceinline__ u64 ffma2(u64 a, u64 b, u64 c) {
    u64 d; asm("fma.rn.f32x2 %0,%1,%2,%3;" : "=l"(d) : "l"(a), "l"(b), "l"(c)); return d;
}
__device__ __forceinline__ u64 fmul2(u64 a, u64 b) {
    u64 d; asm("mul.rn.f32x2 %0,%1,%2;" : "=l"(d) : "l"(a), "l"(b)); return d;
}
__device__ __forceinline__ u32 packbf2(float a, float b) {
    __nv_bfloat162 t = __floats2bfloat162_rn(a, b);
    return *reinterpret_cast<u32*>(&t);
}

// ======================= scratch (__device__ globals) ======================
__device__ float          g_qkv  [(size_t)MTOT * C3];
__device__ __nv_bfloat16  g_xhi  [(size_t)MTOT * CC];
__device__ __nv_bfloat16  g_xlo  [(size_t)MTOT * CC];
__device__ __nv_bfloat16  g_wqT_h[(size_t)C3 * CC];
__device__ __nv_bfloat16  g_wqT_l[(size_t)C3 * CC];
__device__ __nv_bfloat16  g_wpT_h[(size_t)CC * CC];
__device__ __nv_bfloat16  g_wpT_l[(size_t)CC * CC];
__device__ __nv_bfloat16  g_yhi  [(size_t)MTOT * CC];
__device__ __nv_bfloat16  g_ylo  [(size_t)MTOT * CC];

// ======================= conversion kernels ================================
__global__ __launch_bounds__(256)
void conv_split(const float* __restrict__ in,
                __nv_bfloat16* __restrict__ hi, __nv_bfloat16* __restrict__ lo)
{
    size_t i = ((size_t)blockIdx.x * 256 + threadIdx.x) * 4;
    float4 v = *(const float4*)(in + i);
    float h0 = __bfloat162float(__float2bfloat16(v.x));
    float h1 = __bfloat162float(__float2bfloat16(v.y));
    float h2 = __bfloat162float(__float2bfloat16(v.z));
    float h3 = __bfloat162float(__float2bfloat16(v.w));
    uint2 hh = { packbf2(h0, h1), packbf2(h2, h3) };
    uint2 ll = { packbf2(v.x - h0, v.y - h1), packbf2(v.z - h2, v.w - h3) };
    *(uint2*)(hi + i) = hh;
    *(uint2*)(lo + i) = ll;
}

// W [K=1024][N] -> WT hi/lo [N][1024]
__global__ __launch_bounds__(256)
void conv_splitT(const float* __restrict__ W,
                 __nv_bfloat16* __restrict__ hiT, __nv_bfloat16* __restrict__ loT, int N)
{
    __shared__ float tile[32][33];
    int tx = threadIdx.x, ty = threadIdx.y;          // (32, 8)
    int n0 = blockIdx.x * 32, k0 = blockIdx.y * 32;
    #pragma unroll
    for (int i = 0; i < 4; i++)
        tile[ty + 8 * i][tx] = W[(size_t)(k0 + ty + 8 * i) * N + n0 + tx];
    __syncthreads();
    #pragma unroll
    for (int i = 0; i < 4; i++) {
        float v = tile[tx][ty + 8 * i];
        float h = __bfloat162float(__float2bfloat16(v));
        size_t o = (size_t)(n0 + ty + 8 * i) * CC + k0 + tx;
        hiT[o] = __float2bfloat16(v);
        loT[o] = __float2bfloat16(v - h);
    }
}

// ======================= mma.sync GEMM (bf16x3) ============================
// C[M,N_TOTAL] = (Ahi+Alo) @ (Bhi+Blo)^T ; A [M][1024], B [N][1024] K-major.
// 128x128 CTA tile, BK=32, 256 threads, warp grid 4m x 2n (warp tile 32x64).
#define LROW 40   // smem row pitch in bf16 (32 data + 8 pad -> conflict-free ldsm)

template<int N_TOTAL, bool BIAS>
__global__ __launch_bounds__(256)
void gemm_mma(const __nv_bfloat16* __restrict__ Ahi, const __nv_bfloat16* __restrict__ Alo,
              const __nv_bfloat16* __restrict__ Bhi, const __nv_bfloat16* __restrict__ Blo,
              const float* __restrict__ bias, float* __restrict__ C)
{
    __shared__ __nv_bfloat16 sAh[128 * LROW];
    __shared__ __nv_bfloat16 sAl[128 * LROW];
    __shared__ __nv_bfloat16 sBh[128 * LROW];
    __shared__ __nv_bfloat16 sBl[128 * LROW];

    const int tid  = threadIdx.x;
    const int warp = tid >> 5;
    const int lane = tid & 31;
    const int wm   = warp >> 1;          // 0..3  -> m = wm*32
    const int wn   = warp & 1;           // 0..1  -> n = wn*64
    const int m0   = blockIdx.x * 128;
    const int n0   = blockIdx.y * 128;

    // global loads: thread t handles rows (t>>2) and 64+(t>>2), 16B chunk (t&3)
    const int gr = tid >> 2;
    const int gq = tid & 3;

    const size_t aoff0 = (size_t)(m0 + gr) * CC + gq * 8;
    const size_t boff0 = (size_t)(n0 + gr) * CC + gq * 8;
    const size_t rstep = (size_t)64 * CC;

    // smem store offsets (bf16 units)
    const u32 s0 = gr * LROW + gq * 8;
    const u32 s1 = (gr + 64) * LROW + gq * 8;

    // smem bases for ldmatrix
    const u32 bAh = smem_u32(sAh), bAl = smem_u32(sAl);
    const u32 bBh = smem_u32(sBh), bBl = smem_u32(sBl);

    // ldmatrix address components
    const int a_m  = lane & 15;                 // row within m16 tile
    const int a_kh = (lane >> 4) << 3;          // k half: 0 or 8
    const int b_n  = (lane & 7) | ((lane >> 4) << 3);   // 0..15 across two n8 tiles
    const int b_kh = ((lane >> 3) & 1) << 3;

    float acc[2][8][4];
    #pragma unroll
    for (int mi = 0; mi < 2; mi++)
        #pragma unroll
        for (int ni = 0; ni < 8; ni++)
            #pragma unroll
            for (int j = 0; j < 4; j++) acc[mi][ni][j] = 0.0f;

    // preload iter 0
    uint4 pah0 = *(const uint4*)(Ahi + aoff0);
    uint4 pah1 = *(const uint4*)(Ahi + aoff0 + rstep);
    uint4 pal0 = *(const uint4*)(Alo + aoff0);
    uint4 pal1 = *(const uint4*)(Alo + aoff0 + rstep);
    uint4 pbh0 = *(const uint4*)(Bhi + boff0);
    uint4 pbh1 = *(const uint4*)(Bhi + boff0 + rstep);
    uint4 pbl0 = *(const uint4*)(Blo + boff0);
    uint4 pbl1 = *(const uint4*)(Blo + boff0 + rstep);

    const int NK = CC / 32;   // 32 iters
    for (int it = 0; it < NK; it++) {
        *(uint4*)(sAh + s0) = pah0;  *(uint4*)(sAh + s1) = pah1;
        *(uint4*)(sAl + s0) = pal0;  *(uint4*)(sAl + s1) = pal1;
        *(uint4*)(sBh + s0) = pbh0;  *(uint4*)(sBh + s1) = pbh1;
        *(uint4*)(sBl + s0) = pbl0;  *(uint4*)(sBl + s1) = pbl1;
        __syncthreads();

        if (it + 1 < NK) {
            const size_t ao = aoff0 + (size_t)(it + 1) * 32;
            const size_t bo = boff0 + (size_t)(it + 1) * 32;
            pah0 = *(const uint4*)(Ahi + ao); pah1 = *(const uint4*)(Ahi + ao + rstep);
            pal0 = *(const uint4*)(Alo + ao); pal1 = *(const uint4*)(Alo + ao + rstep);
            pbh0 = *(const uint4*)(Bhi + bo); pbh1 = *(const uint4*)(Bhi + bo + rstep);
            pbl0 = *(const uint4*)(Blo + bo); pbl1 = *(const uint4*)(Blo + bo + rstep);
        }

        #pragma unroll
        for (int ks = 0; ks < 2; ks++) {
            const int kc = ks * 16;

            // A fragments (hi, lo): 2 m-tiles each
            u32 ah[2][4], al[2][4];
            #pragma unroll
            for (int mi = 0; mi < 2; mi++) {
                const u32 ro = (u32)((wm * 32 + mi * 16 + a_m) * LROW + kc + a_kh) * 2;
                ldsm_x4(ah[mi][0], ah[mi][1], ah[mi][2], ah[mi][3], bAh + ro);
                ldsm_x4(al[mi][0], al[mi][1], al[mi][2], al[mi][3], bAl + ro);
            }
            // B fragments (hi, lo): 8 n8-tiles each (x4 loads 2 tiles)
            u32 bh[8][2], bl[8][2];
            #pragma unroll
            for (int nt = 0; nt < 4; nt++) {
                const u32 ro = (u32)((wn * 64 + nt * 16 + b_n) * LROW + kc + b_kh) * 2;
                ldsm_x4(bh[2 * nt][0], bh[2 * nt][1], bh[2 * nt + 1][0], bh[2 * nt + 1][1], bBh + ro);
                ldsm_x4(bl[2 * nt][0], bl[2 * nt][1], bl[2 * nt + 1][0], bl[2 * nt + 1][1], bBl + ro);
            }

            #pragma unroll
            for (int mi = 0; mi < 2; mi++)
                #pragma unroll
                for (int ni = 0; ni < 8; ni++) {
                    mma16816(acc[mi][ni], ah[mi], bh[ni]);   // hi*hi
                    mma16816(acc[mi][ni], ah[mi], bl[ni]);   // hi*lo
                    mma16816(acc[mi][ni], al[mi], bh[ni]);   // lo*hi
                }
        }
        __syncthreads();
    }

    // epilogue
    const int l4 = lane >> 2;
    const int l2 = (lane & 3) * 2;
    #pragma unroll
    for (int mi = 0; mi < 2; mi++) {
        const int row = m0 + wm * 32 + mi * 16 + l4;
        #pragma unroll
        for (int ni = 0; ni < 8; ni++) {
            const int col = n0 + wn * 64 + ni * 8 + l2;
            float b0 = 0.f, b1 = 0.f;
            if (BIAS) { b0 = bias[col]; b1 = bias[col + 1]; }
            float2 v0 = { acc[mi][ni][0] + b0, acc[mi][ni][1] + b1 };
            float2 v1 = { acc[mi][ni][2] + b0, acc[mi][ni][3] + b1 };
            *(float2*)(C + (size_t)row * N_TOTAL + col)       = v0;
            *(float2*)(C + (size_t)(row + 8) * N_TOTAL + col) = v1;
        }
    }
}

// ======================= flash attention (fp32) ============================
__global__ __launch_bounds__(128, 3)
void attn64(const float* __restrict__ qkv,
            __nv_bfloat16* __restrict__ yhi, __nv_bfloat16* __restrict__ ylo)
{
    __shared__ float Qt[64][64];
    __shared__ float Kt[64][64];
    __shared__ float Vs[64][64];

    const int tid  = threadIdx.x;
    const int qt   = blockIdx.x & 31;
    const int h    = (blockIdx.x >> 5) & 15;
    const int b    = blockIdx.x >> 9;
    const int ty   = tid >> 3;
    const int tx   = tid & 7;
    const int lane = tid & 31;
    const unsigned src_base = (unsigned)(lane & 24);

    {
        const int r  = tid >> 1;
        const int d0 = (tid & 1) << 5;
        const float* qrow = qkv + ((size_t)(b * TT + qt * 64 + r)) * C3 + h * HDIM + d0;
        #pragma unroll
        for (int i = 0; i < 8; i++) {
            float4 v = *(const float4*)(qrow + 4 * i);
            Qt[d0 + 4 * i + 0][r] = v.x * 0.125f;
            Qt[d0 + 4 * i + 1][r] = v.y * 0.125f;
            Qt[d0 + 4 * i + 2][r] = v.z * 0.125f;
            Qt[d0 + 4 * i + 3][r] = v.w * 0.125f;
        }
    }

    float m_[4], l_[4];
    u64 O2[4][4];
    #pragma unroll
    for (int i = 0; i < 4; i++) {
        m_[i] = -1e30f; l_[i] = 0.0f;
        #pragma unroll
        for (int j = 0; j < 4; j++) O2[i][j] = 0ull;
    }

    for (int kt = 0; kt <= qt; kt++) {
        __syncthreads();
        {
            const int r  = tid >> 1;
            const int d0 = (tid & 1) << 5;
            const float* base = qkv + ((size_t)(b * TT + kt * 64 + r)) * C3 + h * HDIM + d0;
            #pragma unroll
            for (int i = 0; i < 8; i++) {
                float4 kv = *(const float4*)(base + CC + 4 * i);
                Kt[d0 + 4 * i + 0][r] = kv.x;
                Kt[d0 + 4 * i + 1][r] = kv.y;
                Kt[d0 + 4 * i + 2][r] = kv.z;
                Kt[d0 + 4 * i + 3][r] = kv.w;
            }
            #pragma unroll
            for (int i = 0; i < 8; i++)
                *(float4*)&Vs[r][d0 + 4 * i] = *(const float4*)(base + 2 * CC + 4 * i);
        }
        __syncthreads();

        u64 s2[4][4];
        #pragma unroll
        for (int i = 0; i < 4; i++)
            #pragma unroll
            for (int j = 0; j < 4; j++) s2[i][j] = 0ull;

        #pragma unroll 4
        for (int d = 0; d < 64; d++) {
            float4 q4 = *(const float4*)&Qt[d][ty << 2];
            float4 ka = *(const float4*)&Kt[d][tx << 3];
            float4 kb = *(const float4*)&Kt[d][(tx << 3) + 4];
            u64 kk[4] = { pack2(ka.x, ka.y), pack2(ka.z, ka.w),
                          pack2(kb.x, kb.y), pack2(kb.z, kb.w) };
            float qm[4] = { q4.x, q4.y, q4.z, q4.w };
            #pragma unroll
            for (int i = 0; i < 4; i++) {
                u64 q2 = pack2(qm[i], qm[i]);
                #pragma unroll
                for (int j = 0; j < 4; j++)
                    s2[i][j] = ffma2(q2, kk[j], s2[i][j]);
            }
        }

        float p[4][8];
        #pragma unroll
        for (int i = 0; i < 4; i++) {
            #pragma unroll
            for (int j = 0; j < 4; j++) {
                float2 f = unpack2(s2[i][j]);
                p[i][2 * j]     = f.x;
                p[i][2 * j + 1] = f.y;
            }
        }

        if (kt == qt) {
            #pragma unroll
            for (int i = 0; i < 4; i++) {
                const int r = (ty << 2) + i;
                #pragma unroll
                for (int j = 0; j < 8; j++)
                    if ((tx << 3) + j > r) p[i][j] = -1e30f;
            }
        }

        #pragma unroll
        for (int i = 0; i < 4; i++) {
            float mx = p[i][0];
            #pragma unroll
            for (int j = 1; j < 8; j++) mx = fmaxf(mx, p[i][j]);
            mx = fmaxf(mx, __shfl_xor_sync(0xffffffffu, mx, 1));
            mx = fmaxf(mx, __shfl_xor_sync(0xffffffffu, mx, 2));
            mx = fmaxf(mx, __shfl_xor_sync(0xffffffffu, mx, 4));
            float mn = fmaxf(m_[i], mx);
            float al = __expf(m_[i] - mn);
            m_[i] = mn;
            float rs = 0.0f;
            #pragma unroll
            for (int j = 0; j < 8; j++) {
                float e = __expf(p[i][j] - mn);
                p[i][j] = e;
                rs += e;
            }
            rs += __shfl_xor_sync(0xffffffffu, rs, 1);
            rs += __shfl_xor_sync(0xffffffffu, rs, 2);
            rs += __shfl_xor_sync(0xffffffffu, rs, 4);
            l_[i] = l_[i] * al + rs;
            u64 a2 = pack2(al, al);
            #pragma unroll
            for (int j = 0; j < 4; j++) O2[i][j] = fmul2(O2[i][j], a2);
        }

        #pragma unroll 2
        for (int kq = 0; kq < 8; kq++) {
            const unsigned src = src_base + (unsigned)kq;
            #pragma unroll
            for (int kj = 0; kj < 8; kj++) {
                const int key = (kq << 3) + kj;
                float4 va = *(const float4*)&Vs[key][tx << 3];
                float4 vb = *(const float4*)&Vs[key][(tx << 3) + 4];
                u64 vv[4] = { pack2(va.x, va.y), pack2(va.z, va.w),
                              pack2(vb.x, vb.y), pack2(vb.z, vb.w) };
                float pp0 = __shfl_sync(0xffffffffu, p[0][kj], src);
                float pp1 = __shfl_sync(0xffffffffu, p[1][kj], src);
                float pp2 = __shfl_sync(0xffffffffu, p[2][kj], src);
                float pp3 = __shfl_sync(0xffffffffu, p[3][kj], src);
                float pp[4] = { pp0, pp1, pp2, pp3 };
                #pragma unroll
                for (int i = 0; i < 4; i++) {
                    u64 p2 = pack2(pp[i], pp[i]);
                    #pragma unroll
                    for (int j = 0; j < 4; j++)
                        O2[i][j] = ffma2(p2, vv[j], O2[i][j]);
                }
            }
        }
    }

    // normalize + split to bf16 hi/lo for the proj GEMM
    #pragma unroll
    for (int i = 0; i < 4; i++) {
        float inv = 1.0f / l_[i];
        float2 f0 = unpack2(O2[i][0]);
        float2 f1 = unpack2(O2[i][1]);
        float2 f2 = unpack2(O2[i][2]);
        float2 f3 = unpack2(O2[i][3]);
        float o[8] = { f0.x * inv, f0.y * inv, f1.x * inv, f1.y * inv,
                       f2.x * inv, f2.y * inv, f3.x * inv, f3.y * inv };
        float hh[8], ll[8];
        #pragma unroll
        for (int j = 0; j < 8; j++) {
            hh[j] = __bfloat162float(__float2bfloat16(o[j]));
            ll[j] = o[j] - hh[j];
        }
        const int rowi = qt * 64 + (ty << 2) + i;
        size_t off = ((size_t)(b * TT + rowi)) * CC + h * HDIM + (tx << 3);
        uint4 hv = { packbf2(hh[0], hh[1]), packbf2(hh[2], hh[3]),
                     packbf2(hh[4], hh[5]), packbf2(hh[6], hh[7]) };
        uint4 lv = { packbf2(ll[0], ll[1]), packbf2(ll[2], ll[3]),
                     packbf2(ll[4], ll[5]), packbf2(ll[6], ll[7]) };
        *(uint4*)(yhi + off) = hv;
        *(uint4*)(ylo + off) = lv;
    }
}

// ======================= launch ============================================
extern "C" void kernel_launch(void* const* d_in, const int* in_sizes, int n_in,
                              void* d_out, int out_size)
{
    (void)in_sizes; (void)n_in; (void)out_size;
    const float* x      = (const float*)d_in[0];
    const float* w_qkv  = (const float*)d_in[1];
    const float* w_proj = (const float*)d_in[2];
    const float* b_proj = (const float*)d_in[3];
    float* out = (float*)d_out;

    void *pq, *pxh, *pxl, *pwqh, *pwql, *pwph, *pwpl, *pyh, *pyl;
    cudaGetSymbolAddress(&pq,  g_qkv);
    cudaGetSymbolAddress(&pxh, g_xhi);   cudaGetSymbolAddress(&pxl, g_xlo);
    cudaGetSymbolAddress(&pwqh, g_wqT_h); cudaGetSymbolAddress(&pwql, g_wqT_l);
    cudaGetSymbolAddress(&pwph, g_wpT_h); cudaGetSymbolAddress(&pwpl, g_wpT_l);
    cudaGetSymbolAddress(&pyh, g_yhi);   cudaGetSymbolAddress(&pyl, g_ylo);

    // convert x and weights to bf16 hi/lo
    conv_split<<<(MTOT * CC) / (256 * 4), 256>>>(x, (__nv_bfloat16*)pxh, (__nv_bfloat16*)pxl);
    conv_splitT<<<dim3(C3 / 32, CC / 32), dim3(32, 8)>>>(w_qkv, (__nv_bfloat16*)pwqh, (__nv_bfloat16*)pwql, C3);
    conv_splitT<<<dim3(CC / 32, CC / 32), dim3(32, 8)>>>(w_proj, (__nv_bfloat16*)pwph, (__nv_bfloat16*)pwpl, CC);

    // qkv = x @ w_qkv   (mma.sync bf16x3)
    gemm_mma<C3, false><<<dim3(MTOT / 128, C3 / 128), 256>>>(
        (const __nv_bfloat16*)pxh, (const __nv_bfloat16*)pxl,
        (const __nv_bfloat16*)pwqh, (const __nv_bfloat16*)pwql,
        nullptr, (float*)pq);

    // flash attention -> y (bf16 hi/lo)
    attn64<<<BB * HH * (TT / 64), 128>>>((const float*)pq,
                                         (__nv_bfloat16*)pyh, (__nv_bfloat16*)pyl);

    // out = y @ w_proj + b_proj  (mma.sync bf16x3)
    gemm_mma<CC, true><<<dim3(MTOT / 128, CC / 128), 256>>>(
        (const __nv_bfloat16*)pyh, (const __nv_bfloat16*)pyl,
        (const __nv_bfloat16*)pwph, (const __nv_bfloat16*)pwpl,
        b_proj, out);
}